// round 15
// baseline (speedup 1.0000x reference)
#include <cuda_runtime.h>
#include <cuda_fp16.h>

#define NN 8192
#define FF 128
#define PP 16
#define EMAX 262144
#define CAP 128   // per-row list capacity; Poisson(32) => P(overflow) ~ 0

// v16[i] = fp16 concat(nf_i, diff_i) (512B/row, 4MB total, L2-resident)
// act-edge value = pa[src]*dot(nf_src,nf_dst) + gg[src]*dot(d_src,d_dst)
__device__ __half  g_v[NN * 2 * FF];
__device__ float2  g_pg[NN];                 // (alpha_row, gamma_row/F)
__device__ float   g_nb[NN];                 // -beta_row
__device__ int     g_cnt_a[NN], g_cnt_c[NN]; // zero at entry (reset by k4)
__device__ int     g_dst_a[NN * CAP];        // padded per-row act dst lists
__device__ int     g_dst_c[NN * CAP];        // padded per-row cost dst lists

static __device__ __forceinline__ unsigned h2_bits(__half2 h) {
    return *reinterpret_cast<unsigned*>(&h);
}

// ---- K1: blocks [0,1024) prep rows; blocks [1024,2048) bucket edges ----
__global__ void k1_prep_bucket(const float* __restrict__ feature,
                               const float* __restrict__ next_feature,
                               const float* __restrict__ persona_t,
                               const float* __restrict__ alpha,
                               const float* __restrict__ beta,
                               const float* __restrict__ gamma,
                               const int* __restrict__ act_src,
                               const int* __restrict__ act_dst,
                               const int* __restrict__ edge_src,
                               const int* __restrict__ edge_dst,
                               int E, int Ec) {
    int bid = blockIdx.x;
    if (bid >= 1024) {
        int t = (bid - 1024) * blockDim.x + threadIdx.x;
        if (t < E) {
            int s = __ldg(&act_src[t]);
            int p = atomicAdd(&g_cnt_a[s], 1);
            if (p < CAP) g_dst_a[s * CAP + p] = __ldg(&act_dst[t]);
        }
        if (t < Ec) {
            int s = __ldg(&edge_src[t]);
            int p = atomicAdd(&g_cnt_c[s], 1);
            if (p < CAP) g_dst_c[s * CAP + p] = __ldg(&edge_dst[t]);
        }
        return;
    }
    int row  = bid * 8 + (threadIdx.x >> 5);   // 8192 warps, one row each
    int lane = threadIdx.x & 31;

    const float4* nf4 = (const float4*)(next_feature + (size_t)row * FF);
    const float4* f4  = (const float4*)(feature      + (size_t)row * FF);
    float4 nf = nf4[lane];
    float4 f  = f4[lane];
    float4 d  = make_float4(f.x - nf.x, f.y - nf.y, f.z - nf.z, f.w - nf.w);

    float ss = nf.x*nf.x + nf.y*nf.y + nf.z*nf.z + nf.w*nf.w;
    #pragma unroll
    for (int o = 16; o; o >>= 1) ss += __shfl_xor_sync(0xffffffffu, ss, o);
    float inv = rsqrtf(ss);
    nf.x *= inv; nf.y *= inv; nf.z *= inv; nf.w *= inv;
    float s2 = nf.x*nf.x + nf.y*nf.y + nf.z*nf.z + nf.w*nf.w;
    #pragma unroll
    for (int o = 16; o; o >>= 1) s2 += __shfl_xor_sync(0xffffffffu, s2, o);
    float inv2 = rsqrtf(s2);
    nf.x *= inv2; nf.y *= inv2; nf.z *= inv2; nf.w *= inv2;

    float pa = 0.f, pb = 0.f, pg = 0.f;
    if (lane < PP) {
        float p = persona_t[(size_t)row * PP + lane];
        pa = p * alpha[lane];
        pb = p * beta[lane];
        pg = p * gamma[lane];
    }
    #pragma unroll
    for (int o = 16; o; o >>= 1) {
        pa += __shfl_xor_sync(0xffffffffu, pa, o);
        pb += __shfl_xor_sync(0xffffffffu, pb, o);
        pg += __shfl_xor_sync(0xffffffffu, pg, o);
    }
    if (lane == 0) {
        g_pg[row] = make_float2(pa, pg * (1.0f / FF));
        g_nb[row] = -pb;
    }

    uint2* vrow = (uint2*)(g_v + (size_t)row * 2 * FF);
    vrow[lane]      = make_uint2(h2_bits(__floats2half2_rn(nf.x, nf.y)),
                                 h2_bits(__floats2half2_rn(nf.z, nf.w)));
    vrow[32 + lane] = make_uint2(h2_bits(__floats2half2_rn(d.x, d.y)),
                                 h2_bits(__floats2half2_rn(d.z, d.w)));
}

static __device__ __forceinline__ float dot_v(uint4 ap, uint4 bp) {
    float2 a0 = __half22float2(*(__half2*)&ap.x);
    float2 a1 = __half22float2(*(__half2*)&ap.y);
    float2 a2 = __half22float2(*(__half2*)&ap.z);
    float2 a3 = __half22float2(*(__half2*)&ap.w);
    float2 b0 = __half22float2(*(__half2*)&bp.x);
    float2 b1 = __half22float2(*(__half2*)&bp.y);
    float2 b2 = __half22float2(*(__half2*)&bp.z);
    float2 b3 = __half22float2(*(__half2*)&bp.w);
    float s;
    s = a0.x * b0.x;
    s = fmaf(a0.y, b0.y, s);
    s = fmaf(a1.x, b1.x, s);
    s = fmaf(a1.y, b1.y, s);
    s = fmaf(a2.x, b2.x, s);
    s = fmaf(a2.y, b2.y, s);
    s = fmaf(a3.x, b3.x, s);
    s = fmaf(a3.y, b3.y, s);
    return s;
}

// ---- K4: block per row — smem accumulate, then one streaming write ----
__global__ void __launch_bounds__(256) k4_write(float* __restrict__ out) {
    __shared__ float srow[NN];        // 32 KB row accumulator
    __shared__ float sh_nb;
    __shared__ int   sh_na, sh_nc;

    int row  = blockIdx.x;
    int tid  = threadIdx.x;
    int lane = tid & 31, wid = tid >> 5;

    // zero smem row (8 x STS.128 per thread)
    float4* s4 = (float4*)srow;
    float4 z = make_float4(0.f, 0.f, 0.f, 0.f);
    #pragma unroll
    for (int i = 0; i < 8; i++) s4[tid + i * 256] = z;

    if (tid == 0) {
        sh_nb = g_nb[row];
        int na = g_cnt_a[row]; if (na > CAP) na = CAP;
        int nc = g_cnt_c[row]; if (nc > CAP) nc = CAP;
        sh_na = na; sh_nc = nc;
        g_cnt_a[row] = 0; g_cnt_c[row] = 0;   // restore zero-at-entry invariant
    }
    __syncthreads();

    int na = sh_na, nc = sh_nc;
    float2 pg = __ldg(&g_pg[row]);
    float scale = (lane < 16) ? pg.x : pg.y;

    // v[row] once per warp (registers)
    const uint4* vrow = (const uint4*)(g_v + (size_t)row * 2 * FF);
    uint4 ar = vrow[lane];

    // prefetch dst list into lane registers (batches of 32)
    const int* lst_a = g_dst_a + (size_t)row * CAP;
    int idx0 = (lane < na)      ? lst_a[lane]      : 0;
    int idx1 = (32 + lane < na) ? lst_a[32 + lane] : 0;

    // 2-way unrolled over this warp's edges (i = wid, wid+8, ...)
    int i = wid;
    for (; i + 8 < na && i + 8 < 64; i += 16) {
        int e0 = i, e1 = i + 8;
        int d0 = (e0 < 32) ? __shfl_sync(0xffffffffu, idx0, e0)
                           : __shfl_sync(0xffffffffu, idx1, e0 - 32);
        int d1 = (e1 < 32) ? __shfl_sync(0xffffffffu, idx0, e1)
                           : __shfl_sync(0xffffffffu, idx1, e1 - 32);
        uint4 b0 = ((const uint4*)(g_v + (size_t)d0 * 2 * FF))[lane];
        uint4 b1 = ((const uint4*)(g_v + (size_t)d1 * 2 * FF))[lane];
        float r0 = dot_v(ar, b0) * scale;
        float r1 = dot_v(ar, b1) * scale;
        #pragma unroll
        for (int o = 16; o; o >>= 1) {
            r0 += __shfl_xor_sync(0xffffffffu, r0, o);
            r1 += __shfl_xor_sync(0xffffffffu, r1, o);
        }
        if (lane == 0) { atomicAdd(&srow[d0], r0); atomicAdd(&srow[d1], r1); }
    }
    for (; i < na; i += 8) {
        int dst;
        if (i < 32)      dst = __shfl_sync(0xffffffffu, idx0, i);
        else if (i < 64) dst = __shfl_sync(0xffffffffu, idx1, i - 32);
        else             dst = lst_a[i];          // rare tail
        uint4 bp = ((const uint4*)(g_v + (size_t)dst * 2 * FF))[lane];
        float r = dot_v(ar, bp) * scale;
        #pragma unroll
        for (int o = 16; o; o >>= 1) r += __shfl_xor_sync(0xffffffffu, r, o);
        if (lane == 0) atomicAdd(&srow[dst], r);
    }

    // cost edges: one smem atomic per edge (independent, thread-parallel)
    const int* lst_c = g_dst_c + (size_t)row * CAP;
    float nb = sh_nb;
    for (int j = tid; j < nc; j += 256)
        atomicAdd(&srow[lst_c[j]], nb);

    __syncthreads();

    // stream the finished row out (pure STG.128, write-once)
    float4* o4 = (float4*)(out + (size_t)row * NN);
    #pragma unroll
    for (int k = 0; k < 8; k++) o4[tid + k * 256] = s4[tid + k * 256];
}

extern "C" void kernel_launch(void* const* d_in, const int* in_sizes, int n_in,
                              void* d_out, int out_size) {
    const float* feature      = (const float*)d_in[0];
    const float* next_feature = (const float*)d_in[1];
    const float* persona_t    = (const float*)d_in[2];
    const float* alpha        = (const float*)d_in[3];
    const float* beta         = (const float*)d_in[4];
    const float* gamma        = (const float*)d_in[5];
    const int*   act_src      = (const int*)d_in[6];
    const int*   act_dst      = (const int*)d_in[7];
    const int*   edge_src     = (const int*)d_in[8];
    const int*   edge_dst     = (const int*)d_in[9];
    float* out = (float*)d_out;
    int E  = in_sizes[6];
    int Ec = in_sizes[8];

    int bucketb = (max(E, Ec) + 255) / 256;          // 1024 for E=262144
    k1_prep_bucket<<<1024 + bucketb, 256>>>(feature, next_feature, persona_t,
                                            alpha, beta, gamma,
                                            act_src, act_dst, edge_src, edge_dst,
                                            E, Ec);
    k4_write<<<NN, 256>>>(out);
}

// round 16
// speedup vs baseline: 1.0806x; 1.0806x over previous
#include <cuda_runtime.h>
#include <cuda_fp16.h>

#define NN 8192
#define FF 128
#define PP 16
#define EMAX 262144

// v16[i] = fp16 concat(nf_i, diff_i)  (256 halves = 512B/row, 4MB, L2-resident)
// act-edge value = pa[src]*dot(nf_src,nf_dst) + gg[src]*dot(d_src,d_dst)
__device__ __half  g_v[NN * 2 * FF];
__device__ float2  g_pg[NN];      // (alpha_row, gamma_row/F)
__device__ float   g_nb[NN];      // -beta_row
__device__ float   g_val[EMAX];   // per-act-edge values

static __device__ __forceinline__ unsigned h2_bits(__half2 h) {
    return *reinterpret_cast<unsigned*>(&h);
}

// ---------------- prep: warp per row ----------------
__global__ void prep_kernel(const float* __restrict__ feature,
                            const float* __restrict__ next_feature,
                            const float* __restrict__ persona_t,
                            const float* __restrict__ alpha,
                            const float* __restrict__ beta,
                            const float* __restrict__ gamma) {
    int row  = blockIdx.x * 8 + (threadIdx.x >> 5);   // 8192 warps, one row each
    int lane = threadIdx.x & 31;

    const float4* nf4 = (const float4*)(next_feature + (size_t)row * FF);
    const float4* f4  = (const float4*)(feature      + (size_t)row * FF);
    float4 nf = nf4[lane];
    float4 f  = f4[lane];
    float4 d  = make_float4(f.x - nf.x, f.y - nf.y, f.z - nf.z, f.w - nf.w);

    float ss = nf.x*nf.x + nf.y*nf.y + nf.z*nf.z + nf.w*nf.w;
    #pragma unroll
    for (int o = 16; o; o >>= 1) ss += __shfl_xor_sync(0xffffffffu, ss, o);
    float inv = rsqrtf(ss);
    nf.x *= inv; nf.y *= inv; nf.z *= inv; nf.w *= inv;
    float s2 = nf.x*nf.x + nf.y*nf.y + nf.z*nf.z + nf.w*nf.w;
    #pragma unroll
    for (int o = 16; o; o >>= 1) s2 += __shfl_xor_sync(0xffffffffu, s2, o);
    float inv2 = rsqrtf(s2);
    nf.x *= inv2; nf.y *= inv2; nf.z *= inv2; nf.w *= inv2;

    float pa = 0.f, pb = 0.f, pg = 0.f;
    if (lane < PP) {
        float p = persona_t[(size_t)row * PP + lane];
        pa = p * alpha[lane];
        pb = p * beta[lane];
        pg = p * gamma[lane];
    }
    #pragma unroll
    for (int o = 16; o; o >>= 1) {
        pa += __shfl_xor_sync(0xffffffffu, pa, o);
        pb += __shfl_xor_sync(0xffffffffu, pb, o);
        pg += __shfl_xor_sync(0xffffffffu, pg, o);
    }
    if (lane == 0) {
        g_pg[row] = make_float2(pa, pg * (1.0f / FF));
        g_nb[row] = -pb;
    }

    uint2* vrow = (uint2*)(g_v + (size_t)row * 2 * FF);
    vrow[lane]      = make_uint2(h2_bits(__floats2half2_rn(nf.x, nf.y)),
                                 h2_bits(__floats2half2_rn(nf.z, nf.w)));
    vrow[32 + lane] = make_uint2(h2_bits(__floats2half2_rn(d.x, d.y)),
                                 h2_bits(__floats2half2_rn(d.z, d.w)));
}

static __device__ __forceinline__ float pair_dot(int src, int dst, int lane) {
    const uint4* vs = (const uint4*)(g_v + (size_t)src * 2 * FF);
    const uint4* vd = (const uint4*)(g_v + (size_t)dst * 2 * FF);
    uint4 ap = vs[lane];
    uint4 bp = vd[lane];
    float2 a0 = __half22float2(*(__half2*)&ap.x);
    float2 a1 = __half22float2(*(__half2*)&ap.y);
    float2 a2 = __half22float2(*(__half2*)&ap.z);
    float2 a3 = __half22float2(*(__half2*)&ap.w);
    float2 b0 = __half22float2(*(__half2*)&bp.x);
    float2 b1 = __half22float2(*(__half2*)&bp.y);
    float2 b2 = __half22float2(*(__half2*)&bp.z);
    float2 b3 = __half22float2(*(__half2*)&bp.w);
    float s;
    s = a0.x * b0.x;
    s = fmaf(a0.y, b0.y, s);
    s = fmaf(a1.x, b1.x, s);
    s = fmaf(a1.y, b1.y, s);
    s = fmaf(a2.x, b2.x, s);
    s = fmaf(a2.y, b2.y, s);
    s = fmaf(a3.x, b3.x, s);
    s = fmaf(a3.y, b3.y, s);
    float2 pg = __ldg(&g_pg[src]);
    return s * ((lane < 16) ? pg.x : pg.y);   // fp32 src-side scaling
}

// ---- fused: zero stores and edge dots interleaved per iteration ----
// 2048 blocks x 256 threads: 524288 threads (32 float4 zeros each),
// 16384 warps (16 edges each). Per iteration: 2 zero stores + 1 edge.
__global__ void zero_dots_kernel(const int* __restrict__ act_src,
                                 const int* __restrict__ act_dst,
                                 float* __restrict__ out,
                                 long total, int E) {
    long nthreads = (long)gridDim.x * blockDim.x;
    long gid = (long)blockIdx.x * blockDim.x + threadIdx.x;
    int  warp = (int)(gid >> 5);
    int  lane = threadIdx.x & 31;
    const int NW = (int)(nthreads >> 5);

    float4* o4 = (float4*)out;
    float4 z = make_float4(0.f, 0.f, 0.f, 0.f);
    long n4 = total >> 2;

    long zi = gid;          // zero cursor (thread-strided)
    int  e  = warp;         // edge cursor (warp-strided)

    // main interleaved loop: 16 iterations covers 32 zeros + 16 edges
    #pragma unroll 1
    for (int it = 0; it < 16; it++) {
        if (zi < n4) { o4[zi] = z; zi += nthreads; }
        if (zi < n4) { o4[zi] = z; zi += nthreads; }
        if (e < E) {
            int src = __ldg(&act_src[e]);
            int dst = __ldg(&act_dst[e]);
            float r = pair_dot(src, dst, lane);
            #pragma unroll
            for (int o = 16; o; o >>= 1) r += __shfl_xor_sync(0xffffffffu, r, o);
            if (lane == 0) g_val[e] = r;
            e += NW;
        }
    }
    // tails (no-ops for the expected shape)
    for (; zi < n4; zi += nthreads) o4[zi] = z;
    for (long i = (n4 << 2) + gid; i < total; i += nthreads) out[i] = 0.f;
    for (; e < E; e += NW) {
        int src = __ldg(&act_src[e]);
        int dst = __ldg(&act_dst[e]);
        float r = pair_dot(src, dst, lane);
        #pragma unroll
        for (int o = 16; o; o >>= 1) r += __shfl_xor_sync(0xffffffffu, r, o);
        if (lane == 0) g_val[e] = r;
    }
}

// -------- scatter: act values + cost atomics --------
__global__ void scatter_kernel(const int* __restrict__ act_src,
                               const int* __restrict__ act_dst,
                               const int* __restrict__ edge_src,
                               const int* __restrict__ edge_dst,
                               float* __restrict__ out, int E, int Ec) {
    int t = blockIdx.x * blockDim.x + threadIdx.x;
    if (t < E) {
        int src = __ldg(&act_src[t]);
        int dst = __ldg(&act_dst[t]);
        atomicAdd(&out[(size_t)src * NN + dst], g_val[t]);
    } else if (t < E + Ec) {
        int e = t - E;
        int src = __ldg(&edge_src[e]);
        int dst = __ldg(&edge_dst[e]);
        atomicAdd(&out[(size_t)src * NN + dst], g_nb[src]);
    }
}

extern "C" void kernel_launch(void* const* d_in, const int* in_sizes, int n_in,
                              void* d_out, int out_size) {
    const float* feature      = (const float*)d_in[0];
    const float* next_feature = (const float*)d_in[1];
    const float* persona_t    = (const float*)d_in[2];
    const float* alpha        = (const float*)d_in[3];
    const float* beta         = (const float*)d_in[4];
    const float* gamma        = (const float*)d_in[5];
    const int*   act_src      = (const int*)d_in[6];
    const int*   act_dst      = (const int*)d_in[7];
    const int*   edge_src     = (const int*)d_in[8];
    const int*   edge_dst     = (const int*)d_in[9];
    float* out = (float*)d_out;
    int E  = in_sizes[6];
    int Ec = in_sizes[8];

    prep_kernel<<<1024, 256>>>(feature, next_feature, persona_t, alpha, beta, gamma);
    zero_dots_kernel<<<2048, 256>>>(act_src, act_dst, out, (long)out_size, E);
    int st = E + Ec;
    scatter_kernel<<<(st + 255) / 256, 256>>>(act_src, act_dst, edge_src, edge_dst,
                                              out, E, Ec);
}